// round 1
// baseline (speedup 1.0000x reference)
#include <cuda_runtime.h>
#include <cuda_bf16.h>
#include <math.h>

// Problem constants
#define Bq 128
#define Nq 196
#define Fq 512
#define Eq 512
#define Hq 512
#define Aq 512
#define Vq 30000
#define Tq 20   // L-1 steps
#define Lq 21

// ------------------------------------------------------------------
// Device scratch (no allocations allowed; __device__ globals are OK)
// ------------------------------------------------------------------
__device__ float g_emb[Bq * Tq * Eq];          // 5.2 MB
__device__ float g_gfeat[Bq * Fq];
__device__ float g_h[Bq * Hq];
__device__ float g_c[Bq * Hq];
__device__ float g_fproj[Bq * Nq * Aq];        // 51.4 MB
__device__ float g_hproj[Bq * Aq];
__device__ float g_xh[Bq * 1536];              // [emb | ctx | h]
__device__ float g_gates[Bq * 2048];
__device__ float g_Wcat[2048 * 1536];          // 12.6 MB  [W_ih | W_hh]
__device__ float g_bcat[2048];

// ------------------------------------------------------------------
// Generic fp32 SGEMM:  C[M,N] = A[M,K] * B[N,K]^T + bias[N]
// A row-major lda=K, B row-major ldb=K, C row stride ldc.
// BM=128 fixed (all M here are multiples of 128). Tile: 16x16 threads,
// each computes 8 rows x TN cols.  BN = 16*TN.
// ------------------------------------------------------------------
#define BK 16

template<int TN, bool NG>
__global__ __launch_bounds__(256) void gemm_tn(
    const float* __restrict__ A, const float* __restrict__ B,
    const float* __restrict__ bias, float* __restrict__ C,
    int M, int N, int K, int ldc)
{
    constexpr int BN = 16 * TN;
    __shared__ float As[BK][128 + 4];
    __shared__ float Bs[BK][BN + 4];

    const int tid = threadIdx.x;
    const int tx = tid & 15;
    const int ty = tid >> 4;
    const int m0 = blockIdx.y * 128;
    const int n0 = blockIdx.x * BN;

    float acc[8][TN];
#pragma unroll
    for (int i = 0; i < 8; i++)
#pragma unroll
        for (int j = 0; j < TN; j++) acc[i][j] = 0.f;

    const float* Ap = A + (size_t)m0 * K;
    const float* Bp = B + (size_t)n0 * K;

    for (int k0 = 0; k0 < K; k0 += BK) {
        // A tile: 128 rows x 16 cols = 512 float4, 2 per thread
#pragma unroll
        for (int l = 0; l < 2; l++) {
            int idx = tid + l * 256;
            int row = idx >> 2;
            int c4  = idx & 3;
            float4 v = *(const float4*)(Ap + (size_t)row * K + k0 + c4 * 4);
            As[c4 * 4 + 0][row] = v.x;
            As[c4 * 4 + 1][row] = v.y;
            As[c4 * 4 + 2][row] = v.z;
            As[c4 * 4 + 3][row] = v.w;
        }
        // B tile: BN rows x 16 cols = BN*4 float4
        for (int idx = tid; idx < BN * 4; idx += 256) {
            int row = idx >> 2;
            int c4  = idx & 3;
            float4 v = make_float4(0.f, 0.f, 0.f, 0.f);
            if (!NG || (n0 + row) < N)
                v = *(const float4*)(Bp + (size_t)row * K + k0 + c4 * 4);
            Bs[c4 * 4 + 0][row] = v.x;
            Bs[c4 * 4 + 1][row] = v.y;
            Bs[c4 * 4 + 2][row] = v.z;
            Bs[c4 * 4 + 3][row] = v.w;
        }
        __syncthreads();
#pragma unroll
        for (int kk = 0; kk < BK; kk++) {
            float a[8], b[TN];
#pragma unroll
            for (int i = 0; i < 8; i++) a[i] = As[kk][ty * 8 + i];
#pragma unroll
            for (int j = 0; j < TN; j++) b[j] = Bs[kk][tx * TN + j];
#pragma unroll
            for (int i = 0; i < 8; i++)
#pragma unroll
                for (int j = 0; j < TN; j++) acc[i][j] = fmaf(a[i], b[j], acc[i][j]);
        }
        __syncthreads();
    }

#pragma unroll
    for (int i = 0; i < 8; i++) {
        int m = m0 + ty * 8 + i;
#pragma unroll
        for (int j = 0; j < TN; j++) {
            int n = n0 + tx * TN + j;
            if (!NG || n < N)
                C[(size_t)m * ldc + n] = acc[i][j] + bias[n];
        }
    }
}

// ------------------------------------------------------------------
// Weight concat: Wcat[2048,1536] = [W_ih(1024) | W_hh(512)], bcat = b_ih+b_hh
// ------------------------------------------------------------------
__global__ void k_prepw(const float* __restrict__ Wih, const float* __restrict__ Whh,
                        const float* __restrict__ bih, const float* __restrict__ bhh)
{
    int idx = blockIdx.x * blockDim.x + threadIdx.x;
    if (idx < 2048 * 1536) {
        int j = idx / 1536, col = idx % 1536;
        g_Wcat[idx] = (col < 1024) ? Wih[j * 1024 + col] : Whh[j * 512 + (col - 1024)];
    }
    if (idx < 2048) g_bcat[idx] = bih[idx] + bhh[idx];
}

// ------------------------------------------------------------------
// Embedding gather (row 0 forced to zero, matching reference)
// ------------------------------------------------------------------
__global__ void k_embed(const float* __restrict__ eW, const int* __restrict__ cap)
{
    int idx = blockIdx.x * blockDim.x + threadIdx.x;
    if (idx >= Bq * Tq * Eq) return;
    int e  = idx & 511;
    int bt = idx >> 9;
    int b  = bt / Tq, t = bt % Tq;
    int w  = cap[b * Lq + t];
    g_emb[idx] = (w == 0) ? 0.f : eW[(size_t)w * Eq + e];
}

// ------------------------------------------------------------------
// Global feature mean over N
// ------------------------------------------------------------------
__global__ void k_gfeat(const float* __restrict__ feats)
{
    int b = blockIdx.x;
    const float* fe = feats + (size_t)b * Nq * Fq;
    for (int f = threadIdx.x; f < Fq; f += blockDim.x) {
        float acc = 0.f;
        for (int n = 0; n < Nq; n++) acc += fe[n * Fq + f];
        g_gfeat[b * Fq + f] = acc * (1.f / (float)Nq);
    }
}

// ------------------------------------------------------------------
// Fused attention step: scores -> softmax -> ctx; also assemble
// xh = [emb_t | ctx | h] for the gates GEMM.  One block per batch row.
// ------------------------------------------------------------------
__global__ __launch_bounds__(256) void k_attn(
    const float* __restrict__ feats, const float* __restrict__ vw,
    const float* __restrict__ vb, int t)
{
    const int b = blockIdx.x;
    const int tid = threadIdx.x;
    __shared__ float hp[Aq];
    __shared__ float vv[Aq];
    __shared__ float sc[256];
    __shared__ float red[256];

    for (int i = tid; i < Aq; i += 256) {
        hp[i] = g_hproj[b * Aq + i];
        vv[i] = vw[i];
    }
    __syncthreads();

    const float* fp = g_fproj + (size_t)b * Nq * Aq;
    const int lane = tid & 31;
    const int wrp  = tid >> 5;
    for (int n = wrp; n < Nq; n += 8) {
        float s = 0.f;
        const float* row = fp + n * Aq;
        for (int a = lane; a < Aq; a += 32)
            s += vv[a] * tanhf(row[a] + hp[a]);
#pragma unroll
        for (int o = 16; o; o >>= 1) s += __shfl_down_sync(0xffffffff, s, o);
        if (lane == 0) sc[n] = s + vb[0];
    }
    __syncthreads();

    // softmax over 196
    float val = (tid < Nq) ? sc[tid] : -1e30f;
    red[tid] = val;
    __syncthreads();
    for (int o = 128; o; o >>= 1) {
        if (tid < o) red[tid] = fmaxf(red[tid], red[tid + o]);
        __syncthreads();
    }
    float mx = red[0];
    __syncthreads();
    float e = (tid < Nq) ? expf(val - mx) : 0.f;
    red[tid] = e;
    __syncthreads();
    for (int o = 128; o; o >>= 1) {
        if (tid < o) red[tid] += red[tid + o];
        __syncthreads();
    }
    float ssum = red[0];
    __syncthreads();
    if (tid < Nq) sc[tid] = e / ssum;
    __syncthreads();

    // ctx + assemble xh
    const float* fe = feats + (size_t)b * Nq * Fq;
    for (int f = tid; f < Fq; f += 256) {
        float acc = 0.f;
        for (int n = 0; n < Nq; n++) acc = fmaf(sc[n], fe[n * Fq + f], acc);
        g_xh[b * 1536 + 512 + f] = acc;
    }
    for (int i = tid; i < 512; i += 256) {
        g_xh[b * 1536 + i]        = g_emb[((size_t)b * Tq + t) * Eq + i];
        g_xh[b * 1536 + 1024 + i] = g_h[b * Hq + i];
    }
}

// ------------------------------------------------------------------
// LSTM elementwise update
// ------------------------------------------------------------------
__global__ void k_lstm()
{
    int idx = blockIdx.x * blockDim.x + threadIdx.x;  // 65536
    int b = idx >> 9, j = idx & 511;
    const float* g = g_gates + b * 2048;
    float i_ = 1.f / (1.f + expf(-g[j]));
    float f_ = 1.f / (1.f + expf(-g[512 + j]));
    float gg = tanhf(g[1024 + j]);
    float o_ = 1.f / (1.f + expf(-g[1536 + j]));
    float cn = f_ * g_c[idx] + i_ * gg;
    g_c[idx] = cn;
    g_h[idx] = o_ * tanhf(cn);
}

// ------------------------------------------------------------------
// Launch
// ------------------------------------------------------------------
static float* sym(const void* s)
{
    void* p = nullptr;
    cudaGetSymbolAddress(&p, s);
    return (float*)p;
}

extern "C" void kernel_launch(void* const* d_in, const int* in_sizes, int n_in,
                              void* d_out, int out_size)
{
    const float* feats   = (const float*)d_in[0];
    const int*   caps    = (const int*)  d_in[1];
    const float* embW    = (const float*)d_in[2];
    const float* Wf_w    = (const float*)d_in[3];
    const float* Wf_b    = (const float*)d_in[4];
    const float* Wh_w    = (const float*)d_in[5];
    const float* Wh_b    = (const float*)d_in[6];
    const float* v_w     = (const float*)d_in[7];
    const float* v_b     = (const float*)d_in[8];
    const float* W_ih    = (const float*)d_in[9];
    const float* W_hh    = (const float*)d_in[10];
    const float* b_ih    = (const float*)d_in[11];
    const float* b_hh    = (const float*)d_in[12];
    const float* init_w  = (const float*)d_in[13];
    const float* init_b  = (const float*)d_in[14];
    const float* initc_w = (const float*)d_in[15];
    const float* initc_b = (const float*)d_in[16];
    const float* out_w   = (const float*)d_in[17];
    const float* out_b   = (const float*)d_in[18];
    float* out = (float*)d_out;

    float* p_emb   = sym(g_emb);
    float* p_gf    = sym(g_gfeat);
    float* p_h     = sym(g_h);
    float* p_c     = sym(g_c);
    float* p_fproj = sym(g_fproj);
    float* p_hproj = sym(g_hproj);
    float* p_xh    = sym(g_xh);
    float* p_gates = sym(g_gates);
    float* p_Wcat  = sym(g_Wcat);
    float* p_bcat  = sym(g_bcat);
    (void)p_emb;

    // --- prologue (once per call) ---
    k_prepw<<<(2048 * 1536 + 255) / 256, 256>>>(W_ih, W_hh, b_ih, b_hh);
    k_embed<<<(Bq * Tq * Eq + 255) / 256, 256>>>(embW, caps);
    k_gfeat<<<Bq, 256>>>(feats);
    gemm_tn<2, false><<<dim3(16, 1), 256>>>(p_gf, init_w,  init_b,  p_h, Bq, Hq, Fq, Hq);
    gemm_tn<2, false><<<dim3(16, 1), 256>>>(p_gf, initc_w, initc_b, p_c, Bq, Hq, Fq, Hq);
    // fproj: [25088,512] = feats2d @ Wf_w^T
    gemm_tn<8, false><<<dim3(4, 196), 256>>>(feats, Wf_w, Wf_b, p_fproj,
                                             Bq * Nq, Aq, Fq, Aq);

    // --- recurrence ---
    for (int t = 0; t < Tq; t++) {
        gemm_tn<2, false><<<dim3(16, 1), 256>>>(p_h, Wh_w, Wh_b, p_hproj,
                                                Bq, Aq, Hq, Aq);
        k_attn<<<Bq, 256>>>(feats, v_w, v_b, t);
        gemm_tn<2, false><<<dim3(64, 1), 256>>>(p_xh, p_Wcat, p_bcat, p_gates,
                                                Bq, 2048, 1536, 2048);
        k_lstm<<<(Bq * Hq) / 256, 256>>>();
        gemm_tn<8, true><<<dim3((Vq + 127) / 128, 1), 256>>>(
            p_h, out_w, out_b, out + (size_t)t * Vq,
            Bq, Vq, Hq, Tq * Vq);
    }
}

// round 2
// speedup vs baseline: 1.9625x; 1.9625x over previous
#include <cuda_runtime.h>
#include <cuda_bf16.h>
#include <math.h>

#define Bq 128
#define Nq 196
#define Fq 512
#define Eq 512
#define Hq 512
#define Aq 512
#define Vq 30000
#define Tq 20
#define Lq 21

// ------------------------------------------------------------------
// Device scratch
// ------------------------------------------------------------------
__device__ float g_emb[Bq * Tq * Eq];
__device__ float g_gfeat[Bq * Fq];
__device__ float g_h[Bq * Hq];
__device__ float g_c[Bq * Hq];
__device__ float g_fproj[Bq * Nq * Aq];        // 51.4 MB
__device__ float g_xh[Bq * 1536];
__device__ float g_Wcat[2048 * 1536];
__device__ float g_bcat[2048];
__device__ float g_hpart[16 * Bq * 512];       // split-K partials (hproj / h0 / c0)
__device__ float g_gpart[8 * Bq * 2048];       // split-K partials (gates)
__device__ float g_hall[Tq * Bq * Hq];         // all h_t for batched logits

// ------------------------------------------------------------------
// Helpers
// ------------------------------------------------------------------
__device__ __forceinline__ unsigned su32(const void* p) {
    unsigned a;
    asm("{ .reg .u64 t; cvta.to.shared.u64 t, %1; cvt.u32.u64 %0, t; }"
        : "=r"(a) : "l"(p));
    return a;
}
__device__ __forceinline__ void cpa16(unsigned d, const float* s) {
    asm volatile("cp.async.cg.shared.global [%0], [%1], 16;" :: "r"(d), "l"(s));
}
__device__ __forceinline__ unsigned f2tf(float f) {
    unsigned u;
    asm("cvt.rna.tf32.f32 %0, %1;" : "=r"(u) : "f"(f));
    return u;
}
__device__ __forceinline__ float tanh_apx(float x) {
    float y;
    asm("tanh.approx.f32 %0, %1;" : "=f"(y) : "f"(x));
    return y;
}
__device__ __forceinline__ void mma_tf32(float* c, const unsigned* a, const unsigned* b) {
    asm volatile(
        "mma.sync.aligned.m16n8k8.row.col.f32.tf32.tf32.f32 "
        "{%0,%1,%2,%3},{%4,%5,%6,%7},{%8,%9},{%0,%1,%2,%3};"
        : "+f"(c[0]), "+f"(c[1]), "+f"(c[2]), "+f"(c[3])
        : "r"(a[0]), "r"(a[1]), "r"(a[2]), "r"(a[3]), "r"(b[0]), "r"(b[1]));
}

// ------------------------------------------------------------------
// TF32 tensor-core GEMM: C[M,N] = A[M,K] @ B[N,K]^T + bias[N]
// BM=BN=128, BK=16, 256 thr (8 warps 2x4, warp tile 64x32).
// LOGIT: row r of C (r = t*128+b with bm=blockIdx.y*128) scatters to
//        out[b][t][:].  NG: N-guard (clamp loads, guard stores).
// ------------------------------------------------------------------
template<bool LOGIT, bool NG>
__global__ __launch_bounds__(256) void gemm_tf32(
    const float* __restrict__ A, const float* __restrict__ B,
    const float* __restrict__ bias, float* __restrict__ C,
    int N, int K, int ldc)
{
    __shared__ float As[2][128][20];
    __shared__ float Bs[2][128][20];

    const int tid = threadIdx.x;
    const int bm = blockIdx.y * 128;
    const int bn = blockIdx.x * 128;
    const int warp = tid >> 5, lane = tid & 31;
    const int wm = (warp & 1) * 64, wn = (warp >> 1) * 32;
    const int g = lane >> 2, t4 = lane & 3;

    float acc[4][4][4];
#pragma unroll
    for (int i = 0; i < 4; i++)
#pragma unroll
        for (int j = 0; j < 4; j++)
#pragma unroll
            for (int q = 0; q < 4; q++) acc[i][j][q] = 0.f;

    const unsigned sa = su32(As), sb = su32(Bs);

    auto issue = [&](int s, int k0) {
#pragma unroll
        for (int l = 0; l < 2; l++) {
            int i2 = tid + l * 256;
            int row = i2 >> 2, c4 = i2 & 3;
            cpa16(sa + (((unsigned)s * 128 + row) * 20 + c4 * 4) * 4,
                  A + (size_t)(bm + row) * K + k0 + c4 * 4);
            int rb = bn + row;
            if (NG) rb = rb < N ? rb : (N - 1);
            cpa16(sb + (((unsigned)s * 128 + row) * 20 + c4 * 4) * 4,
                  B + (size_t)rb * K + k0 + c4 * 4);
        }
        asm volatile("cp.async.commit_group;");
    };

    const int nk = K / 16;
    issue(0, 0);
    for (int it = 0; it < nk; it++) {
        int s = it & 1;
        asm volatile("cp.async.wait_group 0;");
        __syncthreads();
        if (it + 1 < nk) issue(s ^ 1, (it + 1) * 16);
#pragma unroll
        for (int kk = 0; kk < 2; kk++) {
            unsigned ua[4][4], ub[4][2];
#pragma unroll
            for (int i = 0; i < 4; i++) {
                int r = wm + i * 16 + g;
                ua[i][0] = f2tf(As[s][r][kk * 8 + t4]);
                ua[i][1] = f2tf(As[s][r + 8][kk * 8 + t4]);
                ua[i][2] = f2tf(As[s][r][kk * 8 + t4 + 4]);
                ua[i][3] = f2tf(As[s][r + 8][kk * 8 + t4 + 4]);
            }
#pragma unroll
            for (int j = 0; j < 4; j++) {
                int n = wn + j * 8 + g;
                ub[j][0] = f2tf(Bs[s][n][kk * 8 + t4]);
                ub[j][1] = f2tf(Bs[s][n][kk * 8 + t4 + 4]);
            }
#pragma unroll
            for (int i = 0; i < 4; i++)
#pragma unroll
                for (int j = 0; j < 4; j++)
                    mma_tf32(acc[i][j], ua[i], ub[j]);
        }
        __syncthreads();
    }

    // epilogue
#pragma unroll
    for (int i = 0; i < 4; i++) {
        int r = wm + i * 16 + g;  // local row (and r+8)
#pragma unroll
        for (int j = 0; j < 4; j++) {
            int n = bn + wn + j * 8 + 2 * t4;
            if (NG && n >= N) continue;
            float bz0 = bias[n], bz1 = bias[n + 1];
            float2 v0 = make_float2(acc[i][j][0] + bz0, acc[i][j][1] + bz1);
            float2 v1 = make_float2(acc[i][j][2] + bz0, acc[i][j][3] + bz1);
            if (LOGIT) {
                int tt = blockIdx.y;  // bm = tt*128, b = local row
                *(float2*)(C + (size_t)r * (Tq * (size_t)Vq) + (size_t)tt * Vq + n) = v0;
                *(float2*)(C + (size_t)(r + 8) * (Tq * (size_t)Vq) + (size_t)tt * Vq + n) = v1;
            } else {
                *(float2*)(C + (size_t)(bm + r) * ldc + n) = v0;
                *(float2*)(C + (size_t)(bm + r + 8) * ldc + n) = v1;
            }
        }
    }
}

// ------------------------------------------------------------------
// Split-K fp32 GEMM (M=128 fixed): Cpart[s][128,N] = A[128,Kc] @ B[N,Kc]^T
// BM=BN=128, BK=16, 256 thr, TM=TN=8 (smem-balanced).
// ------------------------------------------------------------------
template<int SPLIT>
__global__ __launch_bounds__(256) void gemm_sk(
    const float* __restrict__ A, const float* __restrict__ B,
    float* __restrict__ Cpart, int N, int K)
{
    __shared__ float As[16][132];
    __shared__ float Bs[16][132];
    const int tid = threadIdx.x;
    const int tx = tid & 15, ty = tid >> 4;
    const int n0 = blockIdx.x * 128;
    const int s = blockIdx.y;
    const int kc = K / SPLIT;
    const int kbeg = s * kc;

    float acc[8][8];
#pragma unroll
    for (int i = 0; i < 8; i++)
#pragma unroll
        for (int j = 0; j < 8; j++) acc[i][j] = 0.f;

    for (int k0 = kbeg; k0 < kbeg + kc; k0 += 16) {
#pragma unroll
        for (int l = 0; l < 2; l++) {
            int i2 = tid + l * 256;
            int m = i2 >> 2, c4 = i2 & 3;
            float4 v = *(const float4*)(A + (size_t)m * K + k0 + c4 * 4);
            As[c4 * 4 + 0][m] = v.x; As[c4 * 4 + 1][m] = v.y;
            As[c4 * 4 + 2][m] = v.z; As[c4 * 4 + 3][m] = v.w;
            float4 w = *(const float4*)(B + (size_t)(n0 + m) * K + k0 + c4 * 4);
            Bs[c4 * 4 + 0][m] = w.x; Bs[c4 * 4 + 1][m] = w.y;
            Bs[c4 * 4 + 2][m] = w.z; Bs[c4 * 4 + 3][m] = w.w;
        }
        __syncthreads();
#pragma unroll
        for (int kk = 0; kk < 16; kk++) {
            float4 a0 = *(const float4*)&As[kk][ty * 8];
            float4 a1 = *(const float4*)&As[kk][ty * 8 + 4];
            float4 b0 = *(const float4*)&Bs[kk][tx * 8];
            float4 b1 = *(const float4*)&Bs[kk][tx * 8 + 4];
            const float av[8] = {a0.x, a0.y, a0.z, a0.w, a1.x, a1.y, a1.z, a1.w};
            const float bv[8] = {b0.x, b0.y, b0.z, b0.w, b1.x, b1.y, b1.z, b1.w};
#pragma unroll
            for (int i = 0; i < 8; i++)
#pragma unroll
                for (int j = 0; j < 8; j++)
                    acc[i][j] = fmaf(av[i], bv[j], acc[i][j]);
        }
        __syncthreads();
    }

    float* Cp = Cpart + (size_t)s * 128 * N;
#pragma unroll
    for (int i = 0; i < 8; i++) {
        float* row = Cp + (size_t)(ty * 8 + i) * N + n0 + tx * 8;
        float4 o0 = make_float4(acc[i][0], acc[i][1], acc[i][2], acc[i][3]);
        float4 o1 = make_float4(acc[i][4], acc[i][5], acc[i][6], acc[i][7]);
        *(float4*)row = o0;
        *(float4*)(row + 4) = o1;
    }
}

// ------------------------------------------------------------------
// Reduce 16 split-K partials (65536 elems): dst = bias[n%512] + sum
// ------------------------------------------------------------------
__global__ void k_red(float* __restrict__ dst, const float* __restrict__ part,
                      const float* __restrict__ bias)
{
    int i = blockIdx.x * 256 + threadIdx.x;
    float acc = bias[i & 511];
#pragma unroll
    for (int s = 0; s < 16; s++) acc += part[s * 65536 + i];
    dst[i] = acc;
}

// ------------------------------------------------------------------
// Weight concat
// ------------------------------------------------------------------
__global__ void k_prepw(const float* __restrict__ Wih, const float* __restrict__ Whh,
                        const float* __restrict__ bih, const float* __restrict__ bhh)
{
    int idx = blockIdx.x * blockDim.x + threadIdx.x;
    if (idx < 2048 * 1536) {
        int j = idx / 1536, col = idx % 1536;
        g_Wcat[idx] = (col < 1024) ? Wih[j * 1024 + col] : Whh[j * 512 + (col - 1024)];
    }
    if (idx < 2048) g_bcat[idx] = bih[idx] + bhh[idx];
}

__global__ void k_embed(const float* __restrict__ eW, const int* __restrict__ cap)
{
    int idx = blockIdx.x * blockDim.x + threadIdx.x;
    if (idx >= Bq * Tq * Eq) return;
    int e = idx & 511;
    int bt = idx >> 9;
    int b = bt / Tq, t = bt % Tq;
    int w = cap[b * Lq + t];
    g_emb[idx] = (w == 0) ? 0.f : eW[(size_t)w * Eq + e];
}

__global__ void k_gfeat(const float* __restrict__ feats)
{
    int b = blockIdx.x;
    const float* fe = feats + (size_t)b * Nq * Fq;
    for (int f = threadIdx.x; f < Fq; f += blockDim.x) {
        float acc = 0.f;
        for (int n = 0; n < Nq; n++) acc += fe[n * Fq + f];
        g_gfeat[b * Fq + f] = acc * (1.f / (float)Nq);
    }
}

// ------------------------------------------------------------------
// Fused attention: reduce hproj partials, scores (MUFU tanh), softmax,
// ctx, assemble xh = [emb_t | ctx | h].  One block per batch row.
// ------------------------------------------------------------------
__global__ __launch_bounds__(256) void k_attn(
    const float* __restrict__ feats, const float* __restrict__ vw,
    const float* __restrict__ vb, const float* __restrict__ whb, int t)
{
    const int b = blockIdx.x;
    const int tid = threadIdx.x;
    __shared__ float hp[Aq];
    __shared__ float vv[Aq];
    __shared__ float sc[256];
    __shared__ float red[256];

    for (int i = tid; i < Aq; i += 256) {
        float s = whb[i];
#pragma unroll
        for (int s2 = 0; s2 < 16; s2++) s += g_hpart[s2 * 65536 + b * 512 + i];
        hp[i] = s;
        vv[i] = vw[i];
    }
    __syncthreads();

    const float* fp = g_fproj + (size_t)b * Nq * Aq;
    const int lane = tid & 31;
    const int wrp = tid >> 5;
    for (int n = wrp; n < Nq; n += 8) {
        float s = 0.f;
        const float4* row = (const float4*)(fp + n * Aq);
        for (int a4 = lane; a4 < 128; a4 += 32) {
            float4 f = row[a4];
            float4 h4 = *(const float4*)&hp[a4 * 4];
            float4 v4 = *(const float4*)&vv[a4 * 4];
            s += v4.x * tanh_apx(f.x + h4.x);
            s += v4.y * tanh_apx(f.y + h4.y);
            s += v4.z * tanh_apx(f.z + h4.z);
            s += v4.w * tanh_apx(f.w + h4.w);
        }
#pragma unroll
        for (int o = 16; o; o >>= 1) s += __shfl_down_sync(0xffffffff, s, o);
        if (lane == 0) sc[n] = s + vb[0];
    }
    __syncthreads();

    float val = (tid < Nq) ? sc[tid] : -1e30f;
    red[tid] = val;
    __syncthreads();
    for (int o = 128; o; o >>= 1) {
        if (tid < o) red[tid] = fmaxf(red[tid], red[tid + o]);
        __syncthreads();
    }
    float mx = red[0];
    __syncthreads();
    float e = (tid < Nq) ? expf(val - mx) : 0.f;
    red[tid] = e;
    __syncthreads();
    for (int o = 128; o; o >>= 1) {
        if (tid < o) red[tid] += red[tid + o];
        __syncthreads();
    }
    float ssum = red[0];
    __syncthreads();
    if (tid < Nq) sc[tid] = e / ssum;
    __syncthreads();

    const float* fe = feats + (size_t)b * Nq * Fq;
    for (int f = tid; f < Fq; f += 256) {
        float acc = 0.f;
#pragma unroll 4
        for (int n = 0; n < Nq; n++) acc = fmaf(sc[n], fe[n * Fq + f], acc);
        g_xh[b * 1536 + 512 + f] = acc;
    }
    for (int i = tid; i < 512; i += 256) {
        g_xh[b * 1536 + i] = g_emb[((size_t)b * Tq + t) * Eq + i];
        g_xh[b * 1536 + 1024 + i] = g_h[b * Hq + i];
    }
}

// ------------------------------------------------------------------
// LSTM update: reduce 8 gate partials, apply activations, write h/c/hall.
// ------------------------------------------------------------------
__global__ void k_lstm(int t)
{
    int idx = blockIdx.x * 256 + threadIdx.x;  // 65536
    int b = idx >> 9, j = idx & 511;
    float v[4];
#pragma unroll
    for (int q = 0; q < 4; q++) {
        float s = g_bcat[q * 512 + j];
#pragma unroll
        for (int s2 = 0; s2 < 8; s2++)
            s += g_gpart[s2 * 262144 + b * 2048 + q * 512 + j];
        v[q] = s;
    }
    float i_ = 1.f / (1.f + expf(-v[0]));
    float f_ = 1.f / (1.f + expf(-v[1]));
    float gg = tanhf(v[2]);
    float o_ = 1.f / (1.f + expf(-v[3]));
    float cn = f_ * g_c[idx] + i_ * gg;
    g_c[idx] = cn;
    float hn = o_ * tanhf(cn);
    g_h[idx] = hn;
    g_hall[((size_t)t * 128 + b) * 512 + j] = hn;
}

// ------------------------------------------------------------------
static float* sym(const void* s)
{
    void* p = nullptr;
    cudaGetSymbolAddress(&p, s);
    return (float*)p;
}

extern "C" void kernel_launch(void* const* d_in, const int* in_sizes, int n_in,
                              void* d_out, int out_size)
{
    const float* feats   = (const float*)d_in[0];
    const int*   caps    = (const int*)  d_in[1];
    const float* embW    = (const float*)d_in[2];
    const float* Wf_w    = (const float*)d_in[3];
    const float* Wf_b    = (const float*)d_in[4];
    const float* Wh_w    = (const float*)d_in[5];
    const float* Wh_b    = (const float*)d_in[6];
    const float* v_w     = (const float*)d_in[7];
    const float* v_b     = (const float*)d_in[8];
    const float* W_ih    = (const float*)d_in[9];
    const float* W_hh    = (const float*)d_in[10];
    const float* b_ih    = (const float*)d_in[11];
    const float* b_hh    = (const float*)d_in[12];
    const float* init_w  = (const float*)d_in[13];
    const float* init_b  = (const float*)d_in[14];
    const float* initc_w = (const float*)d_in[15];
    const float* initc_b = (const float*)d_in[16];
    const float* out_w   = (const float*)d_in[17];
    const float* out_b   = (const float*)d_in[18];
    float* out = (float*)d_out;

    float* p_gf    = sym(g_gfeat);
    float* p_h     = sym(g_h);
    float* p_c     = sym(g_c);
    float* p_fproj = sym(g_fproj);
    float* p_xh    = sym(g_xh);
    float* p_Wcat  = sym(g_Wcat);
    float* p_hpart = sym(g_hpart);
    float* p_gpart = sym(g_gpart);
    float* p_hall  = sym(g_hall);

    // --- prologue ---
    k_prepw<<<(2048 * 1536 + 255) / 256, 256>>>(W_ih, W_hh, b_ih, b_hh);
    k_embed<<<(Bq * Tq * Eq + 255) / 256, 256>>>(embW, caps);
    k_gfeat<<<Bq, 256>>>(feats);
    // h0 = gfeat @ init_w^T + init_b   (split-K 16 + reduce)
    gemm_sk<16><<<dim3(4, 16), 256>>>(p_gf, init_w, p_hpart, 512, 512);
    k_red<<<256, 256>>>(p_h, p_hpart, init_b);
    gemm_sk<16><<<dim3(4, 16), 256>>>(p_gf, initc_w, p_hpart, 512, 512);
    k_red<<<256, 256>>>(p_c, p_hpart, initc_b);
    // fproj = feats2d @ Wf_w^T + Wf_b  (tf32 mma)
    gemm_tf32<false, false><<<dim3(4, 196), 256>>>(feats, Wf_w, Wf_b, p_fproj,
                                                   512, 512, 512);

    // --- recurrence ---
    for (int t = 0; t < Tq; t++) {
        gemm_sk<16><<<dim3(4, 16), 256>>>(p_h, Wh_w, p_hpart, 512, 512);
        k_attn<<<Bq, 256>>>(feats, v_w, v_b, Wh_b, t);
        gemm_sk<8><<<dim3(16, 8), 256>>>(p_xh, p_Wcat, p_gpart, 2048, 1536);
        k_lstm<<<256, 256>>>(t);
    }

    // --- batched logits: [2560,512] @ out_w[30000,512]^T ---
    gemm_tf32<true, true><<<dim3((Vq + 127) / 128, Tq), 256>>>(
        p_hall, out_w, out_b, out, Vq, 512, 0);
}

// round 4
// speedup vs baseline: 2.1145x; 1.0774x over previous
#include <cuda_runtime.h>
#include <cuda_bf16.h>
#include <math.h>

#define Bq 128
#define Nq 196
#define Fq 512
#define Eq 512
#define Hq 512
#define Aq 512
#define Vq 30000
#define Tq 20
#define Lq 21

// ------------------------------------------------------------------
// Device scratch
// ------------------------------------------------------------------
__device__ float g_emb[Bq * Tq * Eq];          // tf32-rounded embeddings
__device__ float g_gfeat[Bq * Fq];
__device__ float g_h[Bq * Hq];                 // tf32-rounded h
__device__ float g_c[Bq * Hq];                 // exact c
__device__ float g_fproj[Bq * Nq * Aq];        // 51.4 MB
__device__ float g_xh[Bq * 1536];              // tf32-rounded [emb|ctx|h]
__device__ float g_Wcat[2048 * 1536];          // tf32-rounded
__device__ float g_bcat[2048];
__device__ float g_hpart[4 * Bq * 512];        // hproj split-K partials
__device__ float g_gpart[8 * Bq * 2048];       // gates split-K partials
__device__ float g_hall[Tq * Bq * Hq];         // tf32-rounded h_t (logits A)
__device__ float g_skpart[16 * Bq * 512];      // h0/c0 split-K partials
__device__ float g_featr[Bq * Nq * Fq];        // tf32-rounded feats
__device__ float g_outwr[Vq * Hq];             // tf32-rounded out_w
__device__ float g_Wfr[Aq * Fq];
__device__ float g_Whr[Aq * Hq];

// ------------------------------------------------------------------
// Helpers
// ------------------------------------------------------------------
__device__ __forceinline__ unsigned su32(const void* p) {
    unsigned a;
    asm("{ .reg .u64 t; cvta.to.shared.u64 t, %1; cvt.u32.u64 %0, t; }"
        : "=r"(a) : "l"(p));
    return a;
}
__device__ __forceinline__ void cpa16(unsigned d, const float* s) {
    asm volatile("cp.async.cg.shared.global [%0], [%1], 16;" :: "r"(d), "l"(s));
}
__device__ __forceinline__ float f2tf(float f) {
    unsigned u;
    asm("cvt.rna.tf32.f32 %0, %1;" : "=r"(u) : "f"(f));
    return __uint_as_float(u);
}
__device__ __forceinline__ float tanh_apx(float x) {
    float y;
    asm("tanh.approx.f32 %0, %1;" : "=f"(y) : "f"(x));
    return y;
}
__device__ __forceinline__ void mma_tf32(float* c, const unsigned* a, const unsigned* b) {
    asm volatile(
        "mma.sync.aligned.m16n8k8.row.col.f32.tf32.tf32.f32 "
        "{%0,%1,%2,%3},{%4,%5,%6,%7},{%8,%9},{%0,%1,%2,%3};"
        : "+f"(c[0]), "+f"(c[1]), "+f"(c[2]), "+f"(c[3])
        : "r"(a[0]), "r"(a[1]), "r"(a[2]), "r"(a[3]), "r"(b[0]), "r"(b[1]));
}

// ------------------------------------------------------------------
// TF32 tensor GEMM on PRE-ROUNDED inputs (no cvt in inner loop).
// Dynamic smem: As[2][128][20] then Bs[2][BN][20].
// C[M,N] = A[M,K] @ B[N,K]^T (+ bias if SPLIT==1)
// BM=128, BK=16, 256 thr = 8 warps (2x4), warp tile 64 x (BN/4).
// SPLIT>1: gridDim.z = SPLIT, partial to C + z*128*N (M==128, no bias).
// LOGIT: row r (= local batch), blockIdx.y = t; scatter C[b][t][:].
// ------------------------------------------------------------------
template<int BN, int SPLIT, bool NG, bool LOGIT>
__global__ __launch_bounds__(256, 1) void gemm_tta(
    const float* __restrict__ A, const float* __restrict__ B,
    const float* __restrict__ bias, float* __restrict__ C,
    int N, int K, int ldc)
{
    constexpr int JF = BN / 32;            // n-frags per warp
    constexpr int AOFF = 0;                // floats
    constexpr int BOFF = 2 * 128 * 20;     // floats
    extern __shared__ float sm[];

    const int tid = threadIdx.x;
    const int bm = blockIdx.y * 128;
    const int bn = blockIdx.x * BN;
    const int warp = tid >> 5, lane = tid & 31;
    const int wm = (warp & 1) * 64, wn = (warp >> 1) * (BN / 4);
    const int g = lane >> 2, t4 = lane & 3;

    const int kc   = K / SPLIT;
    const int kbeg = blockIdx.z * kc;

    float acc[4][JF][4];
#pragma unroll
    for (int i = 0; i < 4; i++)
#pragma unroll
        for (int j = 0; j < JF; j++)
#pragma unroll
            for (int q = 0; q < 4; q++) acc[i][j][q] = 0.f;

    const unsigned sbase = su32(sm);

    auto issue = [&](int s, int k0) {
#pragma unroll
        for (int l = 0; l < 2; l++) {
            int i2 = tid + l * 256;
            int row = i2 >> 2, c4 = i2 & 3;
            cpa16(sbase + (AOFF + ((unsigned)s * 128 + row) * 20 + c4 * 4) * 4,
                  A + (size_t)(bm + row) * K + k0 + c4 * 4);
        }
#pragma unroll
        for (int l = 0; l < BN / 64; l++) {
            int i2 = tid + l * 256;
            int row = i2 >> 2, c4 = i2 & 3;
            int rb = bn + row;
            if (NG) rb = rb < N ? rb : (N - 1);
            cpa16(sbase + (BOFF + ((unsigned)s * BN + row) * 20 + c4 * 4) * 4,
                  B + (size_t)rb * K + k0 + c4 * 4);
        }
        asm volatile("cp.async.commit_group;");
    };

    const int nk = kc / 16;
    issue(0, kbeg);
    for (int it = 0; it < nk; it++) {
        int s = it & 1;
        asm volatile("cp.async.wait_group 0;");
        __syncthreads();
        if (it + 1 < nk) issue(s ^ 1, kbeg + (it + 1) * 16);
        const float* As = sm + AOFF + s * 128 * 20;
        const float* Bs = sm + BOFF + s * BN * 20;
#pragma unroll
        for (int kk = 0; kk < 2; kk++) {
            unsigned ua[4][4], ub[JF][2];
#pragma unroll
            for (int i = 0; i < 4; i++) {
                int r = wm + i * 16 + g;
                ua[i][0] = __float_as_uint(As[r * 20 + kk * 8 + t4]);
                ua[i][1] = __float_as_uint(As[(r + 8) * 20 + kk * 8 + t4]);
                ua[i][2] = __float_as_uint(As[r * 20 + kk * 8 + t4 + 4]);
                ua[i][3] = __float_as_uint(As[(r + 8) * 20 + kk * 8 + t4 + 4]);
            }
#pragma unroll
            for (int j = 0; j < JF; j++) {
                int n = wn + j * 8 + g;
                ub[j][0] = __float_as_uint(Bs[n * 20 + kk * 8 + t4]);
                ub[j][1] = __float_as_uint(Bs[n * 20 + kk * 8 + t4 + 4]);
            }
#pragma unroll
            for (int i = 0; i < 4; i++)
#pragma unroll
                for (int j = 0; j < JF; j++)
                    mma_tf32(acc[i][j], ua[i], ub[j]);
        }
        __syncthreads();
    }

    // epilogue
    float* Cz = (SPLIT > 1) ? (C + (size_t)blockIdx.z * 128 * N) : C;
#pragma unroll
    for (int i = 0; i < 4; i++) {
        int r = wm + i * 16 + g;
#pragma unroll
        for (int j = 0; j < JF; j++) {
            int n = bn + wn + j * 8 + 2 * t4;
            if (NG && n >= N) continue;
            float bz0 = 0.f, bz1 = 0.f;
            if (SPLIT == 1) { bz0 = bias[n]; bz1 = bias[n + 1]; }
            float2 v0 = make_float2(acc[i][j][0] + bz0, acc[i][j][1] + bz1);
            float2 v1 = make_float2(acc[i][j][2] + bz0, acc[i][j][3] + bz1);
            if (LOGIT) {
                int tt = blockIdx.y;
                *(float2*)(Cz + (size_t)r * (Tq * (size_t)Vq) + (size_t)tt * Vq + n) = v0;
                *(float2*)(Cz + (size_t)(r + 8) * (Tq * (size_t)Vq) + (size_t)tt * Vq + n) = v1;
            } else if (SPLIT > 1) {
                *(float2*)(Cz + (size_t)r * N + n) = v0;
                *(float2*)(Cz + (size_t)(r + 8) * N + n) = v1;
            } else {
                *(float2*)(Cz + (size_t)(bm + r) * ldc + n) = v0;
                *(float2*)(Cz + (size_t)(bm + r + 8) * ldc + n) = v1;
            }
        }
    }
}

// ------------------------------------------------------------------
// fp32 split-K GEMM (prologue h0/c0 only)
// ------------------------------------------------------------------
template<int SPLIT>
__global__ __launch_bounds__(256) void gemm_sk(
    const float* __restrict__ A, const float* __restrict__ B,
    float* __restrict__ Cpart, int N, int K)
{
    __shared__ float As[16][132];
    __shared__ float Bs[16][132];
    const int tid = threadIdx.x;
    const int tx = tid & 15, ty = tid >> 4;
    const int n0 = blockIdx.x * 128;
    const int s = blockIdx.y;
    const int kc = K / SPLIT;
    const int kbeg = s * kc;

    float acc[8][8];
#pragma unroll
    for (int i = 0; i < 8; i++)
#pragma unroll
        for (int j = 0; j < 8; j++) acc[i][j] = 0.f;

    for (int k0 = kbeg; k0 < kbeg + kc; k0 += 16) {
#pragma unroll
        for (int l = 0; l < 2; l++) {
            int i2 = tid + l * 256;
            int m = i2 >> 2, c4 = i2 & 3;
            float4 v = *(const float4*)(A + (size_t)m * K + k0 + c4 * 4);
            As[c4 * 4 + 0][m] = v.x; As[c4 * 4 + 1][m] = v.y;
            As[c4 * 4 + 2][m] = v.z; As[c4 * 4 + 3][m] = v.w;
            float4 w = *(const float4*)(B + (size_t)(n0 + m) * K + k0 + c4 * 4);
            Bs[c4 * 4 + 0][m] = w.x; Bs[c4 * 4 + 1][m] = w.y;
            Bs[c4 * 4 + 2][m] = w.z; Bs[c4 * 4 + 3][m] = w.w;
        }
        __syncthreads();
#pragma unroll
        for (int kk = 0; kk < 16; kk++) {
            float4 a0 = *(const float4*)&As[kk][ty * 8];
            float4 a1 = *(const float4*)&As[kk][ty * 8 + 4];
            float4 b0 = *(const float4*)&Bs[kk][tx * 8];
            float4 b1 = *(const float4*)&Bs[kk][tx * 8 + 4];
            const float av[8] = {a0.x, a0.y, a0.z, a0.w, a1.x, a1.y, a1.z, a1.w};
            const float bv[8] = {b0.x, b0.y, b0.z, b0.w, b1.x, b1.y, b1.z, b1.w};
#pragma unroll
            for (int i = 0; i < 8; i++)
#pragma unroll
                for (int j = 0; j < 8; j++)
                    acc[i][j] = fmaf(av[i], bv[j], acc[i][j]);
        }
        __syncthreads();
    }

    float* Cp = Cpart + (size_t)s * 128 * N;
#pragma unroll
    for (int i = 0; i < 8; i++) {
        float* row = Cp + (size_t)(ty * 8 + i) * N + n0 + tx * 8;
        *(float4*)row = make_float4(acc[i][0], acc[i][1], acc[i][2], acc[i][3]);
        *(float4*)(row + 4) = make_float4(acc[i][4], acc[i][5], acc[i][6], acc[i][7]);
    }
}

__global__ void k_red(float* __restrict__ dst, const float* __restrict__ part,
                      const float* __restrict__ bias)
{
    int i = blockIdx.x * 256 + threadIdx.x;
    float acc = bias[i & 511];
#pragma unroll
    for (int s = 0; s < 16; s++) acc += part[s * 65536 + i];
    dst[i] = acc;
}

// ------------------------------------------------------------------
// tf32 pre-rounding copy
// ------------------------------------------------------------------
__global__ void k_round(float* __restrict__ dst, const float* __restrict__ src, int n4)
{
    int i = blockIdx.x * 256 + threadIdx.x;
    if (i >= n4) return;
    float4 v = ((const float4*)src)[i];
    v.x = f2tf(v.x); v.y = f2tf(v.y); v.z = f2tf(v.z); v.w = f2tf(v.w);
    ((float4*)dst)[i] = v;
}

__global__ void k_prepw(const float* __restrict__ Wih, const float* __restrict__ Whh,
                        const float* __restrict__ bih, const float* __restrict__ bhh)
{
    int idx = blockIdx.x * blockDim.x + threadIdx.x;
    if (idx < 2048 * 1536) {
        int j = idx / 1536, col = idx % 1536;
        float w = (col < 1024) ? Wih[j * 1024 + col] : Whh[j * 512 + (col - 1024)];
        g_Wcat[idx] = f2tf(w);
    }
    if (idx < 2048) g_bcat[idx] = bih[idx] + bhh[idx];
}

__global__ void k_embed(const float* __restrict__ eW, const int* __restrict__ cap)
{
    int idx = blockIdx.x * blockDim.x + threadIdx.x;
    if (idx >= Bq * Tq * Eq) return;
    int e = idx & 511;
    int bt = idx >> 9;
    int b = bt / Tq, t = bt % Tq;
    int w = cap[b * Lq + t];
    g_emb[idx] = (w == 0) ? 0.f : f2tf(eW[(size_t)w * Eq + e]);
}

__global__ void k_gfeat(const float* __restrict__ feats)
{
    int b = blockIdx.x;
    const float* fe = feats + (size_t)b * Nq * Fq;
    for (int f = threadIdx.x; f < Fq; f += blockDim.x) {
        float acc = 0.f;
        for (int n = 0; n < Nq; n++) acc += fe[n * Fq + f];
        g_gfeat[b * Fq + f] = acc * (1.f / (float)Nq);
    }
}

// ------------------------------------------------------------------
// Fused attention: reduce 4 hproj partials, scores, softmax, ctx,
// assemble xh (tf32-rounded).  One block per batch row.
// ------------------------------------------------------------------
__global__ __launch_bounds__(256) void k_attn(
    const float* __restrict__ feats, const float* __restrict__ vw,
    const float* __restrict__ vb, const float* __restrict__ whb, int t)
{
    const int b = blockIdx.x;
    const int tid = threadIdx.x;
    __shared__ float hp[Aq];
    __shared__ float vv[Aq];
    __shared__ float sc[256];
    __shared__ float red[256];

    for (int i = tid; i < Aq; i += 256) {
        float s = whb[i];
#pragma unroll
        for (int s2 = 0; s2 < 4; s2++) s += g_hpart[s2 * 65536 + b * 512 + i];
        hp[i] = s;
        vv[i] = vw[i];
    }
    __syncthreads();

    const float* fp = g_fproj + (size_t)b * Nq * Aq;
    const int lane = tid & 31;
    const int wrp = tid >> 5;
    for (int n = wrp; n < Nq; n += 8) {
        float s = 0.f;
        const float4* row = (const float4*)(fp + n * Aq);
        for (int a4 = lane; a4 < 128; a4 += 32) {
            float4 f = row[a4];
            float4 h4 = *(const float4*)&hp[a4 * 4];
            float4 v4 = *(const float4*)&vv[a4 * 4];
            s += v4.x * tanh_apx(f.x + h4.x);
            s += v4.y * tanh_apx(f.y + h4.y);
            s += v4.z * tanh_apx(f.z + h4.z);
            s += v4.w * tanh_apx(f.w + h4.w);
        }
#pragma unroll
        for (int o = 16; o; o >>= 1) s += __shfl_down_sync(0xffffffff, s, o);
        if (lane == 0) sc[n] = s + vb[0];
    }
    __syncthreads();

    float val = (tid < Nq) ? sc[tid] : -1e30f;
    red[tid] = val;
    __syncthreads();
    for (int o = 128; o; o >>= 1) {
        if (tid < o) red[tid] = fmaxf(red[tid], red[tid + o]);
        __syncthreads();
    }
    float mx = red[0];
    __syncthreads();
    float e = (tid < Nq) ? expf(val - mx) : 0.f;
    red[tid] = e;
    __syncthreads();
    for (int o = 128; o; o >>= 1) {
        if (tid < o) red[tid] += red[tid + o];
        __syncthreads();
    }
    float ssum = red[0];
    __syncthreads();
    if (tid < Nq) sc[tid] = e / ssum;
    __syncthreads();

    const float* fe = feats + (size_t)b * Nq * Fq;
    for (int f = tid; f < Fq; f += 256) {
        float acc = 0.f;
#pragma unroll 4
        for (int n = 0; n < Nq; n++) acc = fmaf(sc[n], fe[n * Fq + f], acc);
        g_xh[b * 1536 + 512 + f] = f2tf(acc);
    }
    for (int i = tid; i < 512; i += 256) {
        g_xh[b * 1536 + i] = g_emb[((size_t)b * Tq + t) * Eq + i];   // pre-rounded
        g_xh[b * 1536 + 1024 + i] = g_h[b * Hq + i];                 // pre-rounded
    }
}

// ------------------------------------------------------------------
// LSTM update: reduce 8 gate partials, activations, write h (rounded),
// c (exact), hall (rounded).
// ------------------------------------------------------------------
__global__ void k_lstm(int t)
{
    int idx = blockIdx.x * 256 + threadIdx.x;  // 65536
    int b = idx >> 9, j = idx & 511;
    float v[4];
#pragma unroll
    for (int q = 0; q < 4; q++) {
        float s = g_bcat[q * 512 + j];
#pragma unroll
        for (int s2 = 0; s2 < 8; s2++)
            s += g_gpart[s2 * 262144 + b * 2048 + q * 512 + j];
        v[q] = s;
    }
    float i_ = 1.f / (1.f + expf(-v[0]));
    float f_ = 1.f / (1.f + expf(-v[1]));
    float gg = tanhf(v[2]);
    float o_ = 1.f / (1.f + expf(-v[3]));
    float cn = f_ * g_c[idx] + i_ * gg;
    g_c[idx] = cn;
    float hn = f2tf(o_ * tanhf(cn));
    g_h[idx] = hn;
    g_hall[((size_t)t * 128 + b) * 512 + j] = hn;
}

// ------------------------------------------------------------------
static float* sym(const void* s)
{
    void* p = nullptr;
    cudaGetSymbolAddress(&p, s);
    return (float*)p;
}

extern "C" void kernel_launch(void* const* d_in, const int* in_sizes, int n_in,
                              void* d_out, int out_size)
{
    const float* feats   = (const float*)d_in[0];
    const int*   caps    = (const int*)  d_in[1];
    const float* embW    = (const float*)d_in[2];
    const float* Wf_w    = (const float*)d_in[3];
    const float* Wf_b    = (const float*)d_in[4];
    const float* Wh_w    = (const float*)d_in[5];
    const float* Wh_b    = (const float*)d_in[6];
    const float* v_w     = (const float*)d_in[7];
    const float* v_b     = (const float*)d_in[8];
    const float* W_ih    = (const float*)d_in[9];
    const float* W_hh    = (const float*)d_in[10];
    const float* b_ih    = (const float*)d_in[11];
    const float* b_hh    = (const float*)d_in[12];
    const float* init_w  = (const float*)d_in[13];
    const float* init_b  = (const float*)d_in[14];
    const float* initc_w = (const float*)d_in[15];
    const float* initc_b = (const float*)d_in[16];
    const float* out_w   = (const float*)d_in[17];
    const float* out_b   = (const float*)d_in[18];
    float* out = (float*)d_out;

    float* p_gf    = sym(g_gfeat);
    float* p_h     = sym(g_h);
    float* p_c     = sym(g_c);
    float* p_fproj = sym(g_fproj);
    float* p_xh    = sym(g_xh);
    float* p_Wcat  = sym(g_Wcat);
    float* p_hpart = sym(g_hpart);
    float* p_gpart = sym(g_gpart);
    float* p_hall  = sym(g_hall);
    float* p_skp   = sym(g_skpart);
    float* p_featr = sym(g_featr);
    float* p_outwr = sym(g_outwr);
    float* p_Wfr   = sym(g_Wfr);
    float* p_Whr   = sym(g_Whr);

    constexpr int SM128 = 2 * (128 + 128) * 20 * 4;  // 40960
    constexpr int SM256 = 2 * (128 + 256) * 20 * 4;  // 61440
    static bool attr_done = false;
    if (!attr_done) {
        cudaFuncSetAttribute((const void*)gemm_tta<256, 1, false, false>,
                             cudaFuncAttributeMaxDynamicSharedMemorySize, SM256);
        cudaFuncSetAttribute((const void*)gemm_tta<256, 8, false, false>,
                             cudaFuncAttributeMaxDynamicSharedMemorySize, SM256);
        cudaFuncSetAttribute((const void*)gemm_tta<256, 1, true, true>,
                             cudaFuncAttributeMaxDynamicSharedMemorySize, SM256);
        cudaFuncSetAttribute((const void*)gemm_tta<128, 4, false, false>,
                             cudaFuncAttributeMaxDynamicSharedMemorySize, SM128);
        attr_done = true;
    }

    // --- prologue: prep + tf32 pre-rounding ---
    k_prepw<<<(2048 * 1536 + 255) / 256, 256>>>(W_ih, W_hh, b_ih, b_hh);
    k_embed<<<(Bq * Tq * Eq + 255) / 256, 256>>>(embW, caps);
    k_gfeat<<<Bq, 256>>>(feats);
    k_round<<<(Bq * Nq * Fq / 4 + 255) / 256, 256>>>(p_featr, feats, Bq * Nq * Fq / 4);
    k_round<<<(Vq * Hq / 4 + 255) / 256, 256>>>(p_outwr, out_w, Vq * Hq / 4);
    k_round<<<(Aq * Fq / 4 + 255) / 256, 256>>>(p_Wfr, Wf_w, Aq * Fq / 4);
    k_round<<<(Aq * Hq / 4 + 255) / 256, 256>>>(p_Whr, Wh_w, Aq * Hq / 4);

    gemm_sk<16><<<dim3(4, 16), 256>>>(p_gf, init_w, p_skp, 512, 512);
    k_red<<<256, 256>>>(p_h, p_skp, init_b);
    gemm_sk<16><<<dim3(4, 16), 256>>>(p_gf, initc_w, p_skp, 512, 512);
    k_red<<<256, 256>>>(p_c, p_skp, initc_b);

    // fproj = featr @ Wfr^T + Wf_b   (tf32, BN=256)
    gemm_tta<256, 1, false, false><<<dim3(2, 196, 1), 256, SM256>>>(
        p_featr, p_Wfr, Wf_b, p_fproj, 512, 512, 512);

    // --- recurrence ---
    for (int t = 0; t < Tq; t++) {
        gemm_tta<128, 4, false, false><<<dim3(4, 1, 4), 256, SM128>>>(
            p_h, p_Whr, nullptr, p_hpart, 512, 512, 0);
        k_attn<<<Bq, 256>>>(feats, v_w, v_b, Wh_b, t);
        gemm_tta<256, 8, false, false><<<dim3(8, 1, 8), 256, SM256>>>(
            p_xh, p_Wcat, nullptr, p_gpart, 2048, 1536, 0);
        k_lstm<<<256, 256>>>(t);
    }

    // --- batched logits: [2560,512] @ outwr[30000,512]^T  (tf32, BN=256) ---
    gemm_tta<256, 1, true, true><<<dim3((Vq + 255) / 256, Tq, 1), 256, SM256>>>(
        p_hall, p_outwr, out_b, out, Vq, 512, 0);
}